// round 5
// baseline (speedup 1.0000x reference)
#include <cuda_runtime.h>
#include <cstdint>
#include <math_constants.h>

// ---------------- problem-size constants ----------------
#define MAXN 50000
#define MAXE 800000
#define MAXET (MAXE + MAXN)   // edges + self loops
#define NG 64                 // graphs

// ---------------- scratch (device globals; allocation-free) ----------------
__device__ float g_xs1[(size_t)MAXN * 256];
__device__ float g_xd1[(size_t)MAXN * 256];
__device__ float g_h  [(size_t)MAXN * 256];
__device__ float g_xs2[(size_t)MAXN * 64];
__device__ float g_xd2[(size_t)MAXN * 64];

__device__ int   g_deg[MAXN];
__device__ int   g_rowptr[MAXN + 1];
__device__ int   g_cursor[MAXN];
__device__ int   g_csr_src[MAXET];

__device__ float g_pool[NG * 64];
__device__ float g_cnt[NG];

__device__ __forceinline__ float lrelu(float v) {
    return v > 0.0f ? v : 0.2f * v;
}

__device__ __forceinline__ unsigned f2tf32(float f) {
    unsigned r;
    asm("cvt.rna.tf32.f32 %0, %1;" : "=r"(r) : "f"(f));
    return r;
}

__device__ __forceinline__ void mma_tf32(float* c, const unsigned* a, const unsigned* b) {
    asm volatile(
        "mma.sync.aligned.m16n8k8.row.col.f32.tf32.tf32.f32 "
        "{%0,%1,%2,%3}, {%4,%5,%6,%7}, {%8,%9}, {%0,%1,%2,%3};"
        : "+f"(c[0]), "+f"(c[1]), "+f"(c[2]), "+f"(c[3])
        : "r"(a[0]), "r"(a[1]), "r"(a[2]), "r"(a[3]), "r"(b[0]), "r"(b[1]));
}

// ---------------- zero / init ----------------
__global__ void zero_kernel(int N) {
    int i = blockIdx.x * blockDim.x + threadIdx.x;
    int stride = gridDim.x * blockDim.x;
    for (int k = i; k < N; k += stride) g_deg[k] = 0;
    if (i < NG * 64) g_pool[i] = 0.0f;
    if (i < NG)      g_cnt[i] = 0.0f;
}

// ---------------- CSR build ----------------
__global__ void hist_kernel(const int* __restrict__ ei, int E, int N) {
    int i = blockIdx.x * blockDim.x + threadIdx.x;
    int ET = E + N;
    if (i >= ET) return;
    int d = (i < E) ? ei[E + i] : (i - E);
    atomicAdd(&g_deg[d], 1);
}

__global__ void scan_kernel(int N) {
    __shared__ int ssum[1024];
    int t = threadIdx.x;
    int chunk = (N + 1023) >> 10;
    int b = t * chunk;
    int e = b + chunk; if (e > N) e = N;
    int s = 0;
    for (int i = b; i < e; i++) s += g_deg[i];
    ssum[t] = s;
    __syncthreads();
    for (int off = 1; off < 1024; off <<= 1) {
        int v = (t >= off) ? ssum[t - off] : 0;
        __syncthreads();
        ssum[t] += v;
        __syncthreads();
    }
    int run = (t == 0) ? 0 : ssum[t - 1];
    for (int i = b; i < e; i++) {
        g_rowptr[i] = run;
        g_cursor[i] = run;
        run += g_deg[i];
    }
    if (t == 1023) g_rowptr[N] = ssum[1023];
}

__global__ void scatter_kernel(const int* __restrict__ ei, int E, int N) {
    int i = blockIdx.x * blockDim.x + threadIdx.x;
    int ET = E + N;
    if (i >= ET) return;
    int s, d;
    if (i < E) { s = ei[i]; d = ei[E + i]; }
    else       { s = i - E; d = s; }
    int pos = atomicAdd(&g_cursor[d], 1);
    g_csr_src[pos] = s;
}

// ---------------- tf32 tensor-core GEMM ----------------
// C[M,Ncol] = A[M,K] @ W[K,Ncol] + bias
// Tile: BM=128, BN=64, BK=32; 256 threads = 8 warps (4m x 2n).
// smem holds PRE-CONVERTED tf32 (unsigned) so the inner loop is pure LDS+MMA.
// blockIdx.z selects (W0,b0,C0) vs (W1,b1,C1).
__global__ void gemm_tf32_dual(const float* __restrict__ A,
                               const float* __restrict__ W0, const float* __restrict__ b0,
                               float* __restrict__ C0,
                               const float* __restrict__ W1, const float* __restrict__ b1,
                               float* __restrict__ C1,
                               int M, int K, int Ncol) {
    const float* W    = blockIdx.z ? W1 : W0;
    const float* bias = blockIdx.z ? b1 : b0;
    float*       C    = blockIdx.z ? C1 : C0;

    __shared__ unsigned As[128][36];   // stride 36: conflict-free frag loads
    __shared__ unsigned Bs[32][68];

    const int t    = threadIdx.x;
    const int lane = t & 31;
    const int warp = t >> 5;
    const int grp  = lane >> 2;   // 0..7
    const int tg   = lane & 3;    // 0..3
    const int warp_m = warp & 3;  // 4 warps along M (32 rows each)
    const int warp_n = warp >> 2; // 2 warps along N (32 cols each)

    const int row0 = blockIdx.y * 128;
    const int col0 = blockIdx.x * 64;

    float acc[2][4][4];
#pragma unroll
    for (int mi = 0; mi < 2; mi++)
#pragma unroll
        for (int ni = 0; ni < 4; ni++)
#pragma unroll
            for (int j = 0; j < 4; j++) acc[mi][ni][j] = 0.0f;

    for (int k0 = 0; k0 < K; k0 += 32) {
        // A tile: 128 rows x 32 cols = 1024 float4 over 256 threads (convert at store)
#pragma unroll
        for (int i = 0; i < 4; i++) {
            int idx = t + i * 256;
            int r  = idx >> 3;
            int c4 = idx & 7;
            int gr = row0 + r;
            float4 v = make_float4(0.f, 0.f, 0.f, 0.f);
            if (gr < M)
                v = *reinterpret_cast<const float4*>(&A[(size_t)gr * K + k0 + c4 * 4]);
            uint4 u = make_uint4(f2tf32(v.x), f2tf32(v.y), f2tf32(v.z), f2tf32(v.w));
            *reinterpret_cast<uint4*>(&As[r][c4 * 4]) = u;
        }
        // B tile: 32 rows x 64 cols = 512 float4
#pragma unroll
        for (int i = 0; i < 2; i++) {
            int idx = t + i * 256;
            int kk = idx >> 4;
            int c4 = idx & 15;
            float4 v = *reinterpret_cast<const float4*>(&W[(size_t)(k0 + kk) * Ncol + col0 + c4 * 4]);
            uint4 u = make_uint4(f2tf32(v.x), f2tf32(v.y), f2tf32(v.z), f2tf32(v.w));
            *reinterpret_cast<uint4*>(&Bs[kk][c4 * 4]) = u;
        }
        __syncthreads();

#pragma unroll
        for (int ks = 0; ks < 32; ks += 8) {
            unsigned af[2][4];
#pragma unroll
            for (int mi = 0; mi < 2; mi++) {
                int r = warp_m * 32 + mi * 16 + grp;
                af[mi][0] = As[r][ks + tg];
                af[mi][1] = As[r + 8][ks + tg];
                af[mi][2] = As[r][ks + tg + 4];
                af[mi][3] = As[r + 8][ks + tg + 4];
            }
            unsigned bf[4][2];
#pragma unroll
            for (int ni = 0; ni < 4; ni++) {
                int c = warp_n * 32 + ni * 8 + grp;
                bf[ni][0] = Bs[ks + tg][c];
                bf[ni][1] = Bs[ks + tg + 4][c];
            }
#pragma unroll
            for (int mi = 0; mi < 2; mi++)
#pragma unroll
                for (int ni = 0; ni < 4; ni++)
                    mma_tf32(acc[mi][ni], af[mi], bf[ni]);
        }
        __syncthreads();
    }

#pragma unroll
    for (int ni = 0; ni < 4; ni++) {
        int gc = col0 + warp_n * 32 + ni * 8 + tg * 2;
        float2 bv = *reinterpret_cast<const float2*>(&bias[gc]);
#pragma unroll
        for (int mi = 0; mi < 2; mi++) {
            int gr = row0 + warp_m * 32 + mi * 16 + grp;
            if (gr < M) {
                float2 o = make_float2(acc[mi][ni][0] + bv.x, acc[mi][ni][1] + bv.y);
                *reinterpret_cast<float2*>(&C[(size_t)gr * Ncol + gc]) = o;
            }
            if (gr + 8 < M) {
                float2 o = make_float2(acc[mi][ni][2] + bv.x, acc[mi][ni][3] + bv.y);
                *reinterpret_cast<float2*>(&C[(size_t)(gr + 8) * Ncol + gc]) = o;
            }
        }
    }
}

// ---------------- fused layer-1 node pass (H=4, C=64) ----------------
// one warp per dst node; 2-edge-unrolled online softmax; bias+relu epilogue.
__global__ void fused_gat1(const float* __restrict__ att,
                           const float* __restrict__ bias, int N) {
    int warp = (blockIdx.x * blockDim.x + threadIdx.x) >> 5;
    if (warp >= N) return;
    int lane = threadIdx.x & 31;
    int n = warp;
    int c0 = lane * 8;

    const float4* xdp = reinterpret_cast<const float4*>(g_xd1 + (size_t)n * 256 + c0);
    float4 d0 = xdp[0], d1 = xdp[1];
    float4 w0 = *reinterpret_cast<const float4*>(att + c0);
    float4 w1 = *reinterpret_cast<const float4*>(att + c0 + 4);

    float m = -CUDART_INF_F, s = 0.0f;
    float acc[8] = {0, 0, 0, 0, 0, 0, 0, 0};

    int beg = g_rowptr[n], end = g_rowptr[n + 1];
    int e = beg;
    for (; e + 1 < end; e += 2) {
        int s0 = g_csr_src[e];
        int s1 = g_csr_src[e + 1];
        const float4* x0 = reinterpret_cast<const float4*>(g_xs1 + (size_t)s0 * 256 + c0);
        const float4* x1 = reinterpret_cast<const float4*>(g_xs1 + (size_t)s1 * 256 + c0);
        float4 a00 = x0[0], a01 = x0[1];
        float4 a10 = x1[0], a11 = x1[1];

        float p0 = lrelu(a00.x + d0.x) * w0.x + lrelu(a00.y + d0.y) * w0.y
                 + lrelu(a00.z + d0.z) * w0.z + lrelu(a00.w + d0.w) * w0.w
                 + lrelu(a01.x + d1.x) * w1.x + lrelu(a01.y + d1.y) * w1.y
                 + lrelu(a01.z + d1.z) * w1.z + lrelu(a01.w + d1.w) * w1.w;
        float p1 = lrelu(a10.x + d0.x) * w0.x + lrelu(a10.y + d0.y) * w0.y
                 + lrelu(a10.z + d0.z) * w0.z + lrelu(a10.w + d0.w) * w0.w
                 + lrelu(a11.x + d1.x) * w1.x + lrelu(a11.y + d1.y) * w1.y
                 + lrelu(a11.z + d1.z) * w1.z + lrelu(a11.w + d1.w) * w1.w;
        p0 += __shfl_xor_sync(0xffffffffu, p0, 4);
        p1 += __shfl_xor_sync(0xffffffffu, p1, 4);
        p0 += __shfl_xor_sync(0xffffffffu, p0, 2);
        p1 += __shfl_xor_sync(0xffffffffu, p1, 2);
        p0 += __shfl_xor_sync(0xffffffffu, p0, 1);
        p1 += __shfl_xor_sync(0xffffffffu, p1, 1);

        float mp = fmaxf(p0, p1);
        float m_new = fmaxf(m, mp);
        float scale = __expf(m - m_new);     // 0 on first pair (m=-inf)
        float e0 = __expf(p0 - m_new);
        float e1 = __expf(p1 - m_new);
        s = s * scale + e0 + e1;
        acc[0] = acc[0] * scale + e0 * a00.x + e1 * a10.x;
        acc[1] = acc[1] * scale + e0 * a00.y + e1 * a10.y;
        acc[2] = acc[2] * scale + e0 * a00.z + e1 * a10.z;
        acc[3] = acc[3] * scale + e0 * a00.w + e1 * a10.w;
        acc[4] = acc[4] * scale + e0 * a01.x + e1 * a11.x;
        acc[5] = acc[5] * scale + e0 * a01.y + e1 * a11.y;
        acc[6] = acc[6] * scale + e0 * a01.z + e1 * a11.z;
        acc[7] = acc[7] * scale + e0 * a01.w + e1 * a11.w;
        m = m_new;
    }
    if (e < end) {   // tail edge
        int s0 = g_csr_src[e];
        const float4* x0 = reinterpret_cast<const float4*>(g_xs1 + (size_t)s0 * 256 + c0);
        float4 a00 = x0[0], a01 = x0[1];
        float p0 = lrelu(a00.x + d0.x) * w0.x + lrelu(a00.y + d0.y) * w0.y
                 + lrelu(a00.z + d0.z) * w0.z + lrelu(a00.w + d0.w) * w0.w
                 + lrelu(a01.x + d1.x) * w1.x + lrelu(a01.y + d1.y) * w1.y
                 + lrelu(a01.z + d1.z) * w1.z + lrelu(a01.w + d1.w) * w1.w;
        p0 += __shfl_xor_sync(0xffffffffu, p0, 4);
        p0 += __shfl_xor_sync(0xffffffffu, p0, 2);
        p0 += __shfl_xor_sync(0xffffffffu, p0, 1);
        float m_new = fmaxf(m, p0);
        float scale = __expf(m - m_new);
        float e0 = __expf(p0 - m_new);
        s = s * scale + e0;
        acc[0] = acc[0] * scale + e0 * a00.x;
        acc[1] = acc[1] * scale + e0 * a00.y;
        acc[2] = acc[2] * scale + e0 * a00.z;
        acc[3] = acc[3] * scale + e0 * a00.w;
        acc[4] = acc[4] * scale + e0 * a01.x;
        acc[5] = acc[5] * scale + e0 * a01.y;
        acc[6] = acc[6] * scale + e0 * a01.z;
        acc[7] = acc[7] * scale + e0 * a01.w;
    }

    float inv = 1.0f / s;
    float4 b0 = *reinterpret_cast<const float4*>(bias + c0);
    float4 b1 = *reinterpret_cast<const float4*>(bias + c0 + 4);
    float4 o0, o1;
    o0.x = fmaxf(acc[0] * inv + b0.x, 0.0f);
    o0.y = fmaxf(acc[1] * inv + b0.y, 0.0f);
    o0.z = fmaxf(acc[2] * inv + b0.z, 0.0f);
    o0.w = fmaxf(acc[3] * inv + b0.w, 0.0f);
    o1.x = fmaxf(acc[4] * inv + b1.x, 0.0f);
    o1.y = fmaxf(acc[5] * inv + b1.y, 0.0f);
    o1.z = fmaxf(acc[6] * inv + b1.z, 0.0f);
    o1.w = fmaxf(acc[7] * inv + b1.w, 0.0f);
    float4* hp = reinterpret_cast<float4*>(g_h + (size_t)n * 256 + c0);
    hp[0] = o0;
    hp[1] = o1;
}

// ---------------- fused layer-2 node pass (H=1, C=64) + pool ----------------
// half-warp (16 lanes x float4) per node; 2 nodes per warp.
__global__ void fused_gat2(const float* __restrict__ att,
                           const float* __restrict__ bias,
                           const int* __restrict__ batch, int N) {
    int warp = (blockIdx.x * blockDim.x + threadIdx.x) >> 5;
    int lane = threadIdx.x & 31;
    int half = lane >> 4;
    int sl   = lane & 15;
    int n = warp * 2 + half;
    bool nvalid = (n < N);
    int nn = nvalid ? n : 0;
    int c0 = sl * 4;

    float4 d = *reinterpret_cast<const float4*>(g_xd2 + (size_t)nn * 64 + c0);
    float4 w = *reinterpret_cast<const float4*>(att + c0);

    float m = -CUDART_INF_F, s = 0.0f;
    float acc0 = 0.f, acc1 = 0.f, acc2 = 0.f, acc3 = 0.f;

    int beg = nvalid ? g_rowptr[nn]     : 0;
    int end = nvalid ? g_rowptr[nn + 1] : 0;
    int len = end - beg;
    int olen = __shfl_xor_sync(0xffffffffu, len, 16);
    int maxlen = max(len, olen);

    for (int i = 0; i < maxlen; i++) {
        bool v = (i < len);
        int src = v ? g_csr_src[beg + i] : 0;
        float4 a = make_float4(0.f, 0.f, 0.f, 0.f);
        if (v) a = *reinterpret_cast<const float4*>(g_xs2 + (size_t)src * 64 + c0);
        float p = v ? (lrelu(a.x + d.x) * w.x + lrelu(a.y + d.y) * w.y
                     + lrelu(a.z + d.z) * w.z + lrelu(a.w + d.w) * w.w)
                    : -CUDART_INF_F;
        p += __shfl_xor_sync(0xffffffffu, p, 8);
        p += __shfl_xor_sync(0xffffffffu, p, 4);
        p += __shfl_xor_sync(0xffffffffu, p, 2);
        p += __shfl_xor_sync(0xffffffffu, p, 1);
        // invalid iterations give p=-inf; they occur only after >=1 valid one
        // (every node has a self loop), so m stays finite and ex=0.
        float m_new = fmaxf(m, p);
        float scale = __expf(m - m_new);
        float ex    = __expf(p - m_new);
        s = s * scale + ex;
        acc0 = acc0 * scale + ex * a.x;
        acc1 = acc1 * scale + ex * a.y;
        acc2 = acc2 * scale + ex * a.z;
        acc3 = acc3 * scale + ex * a.w;
        m = m_new;
    }

    if (nvalid) {
        float inv = 1.0f / s;
        float4 bv = *reinterpret_cast<const float4*>(bias + c0);
        int g = batch[nn];
        atomicAdd(&g_pool[g * 64 + c0 + 0], acc0 * inv + bv.x);
        atomicAdd(&g_pool[g * 64 + c0 + 1], acc1 * inv + bv.y);
        atomicAdd(&g_pool[g * 64 + c0 + 2], acc2 * inv + bv.z);
        atomicAdd(&g_pool[g * 64 + c0 + 3], acc3 * inv + bv.w);
        if (sl == 0) atomicAdd(&g_cnt[g], 1.0f);
    }
}

__global__ void final_kernel(const float* __restrict__ Wlin,
                             const float* __restrict__ blin,
                             float* __restrict__ out) {
    int g = threadIdx.x;
    if (g >= NG) return;
    float cnt = g_cnt[g];
    if (cnt < 1.0f) cnt = 1.0f;
    float sum = 0.0f;
#pragma unroll
    for (int c = 0; c < 64; c++)
        sum += (g_pool[g * 64 + c] / cnt) * Wlin[c];
    out[g] = sum + blin[0];
}

// ---------------- launcher ----------------
extern "C" void kernel_launch(void* const* d_in, const int* in_sizes, int n_in,
                              void* d_out, int out_size) {
    const float* x      = (const float*)d_in[0];
    const int*   ei     = (const int*)d_in[1];
    const int*   batch  = (const int*)d_in[2];
    const float* W_l1   = (const float*)d_in[3];
    const float* b_l1   = (const float*)d_in[4];
    const float* W_r1   = (const float*)d_in[5];
    const float* b_r1   = (const float*)d_in[6];
    const float* att1   = (const float*)d_in[7];
    const float* bias1  = (const float*)d_in[8];
    const float* W_l2   = (const float*)d_in[9];
    const float* b_l2   = (const float*)d_in[10];
    const float* W_r2   = (const float*)d_in[11];
    const float* b_r2   = (const float*)d_in[12];
    const float* att2   = (const float*)d_in[13];
    const float* bias2  = (const float*)d_in[14];
    const float* W_lin  = (const float*)d_in[15];
    const float* b_lin  = (const float*)d_in[16];
    float* out = (float*)d_out;

    const int N = in_sizes[0] / 128;   // 50000
    const int E = in_sizes[1] / 2;     // 800000
    const int ET = E + N;

    // __device__ symbols -> real device pointers (host-side query; capture-safe)
    float *p_xs1, *p_xd1, *p_h, *p_xs2, *p_xd2;
    cudaGetSymbolAddress((void**)&p_xs1, g_xs1);
    cudaGetSymbolAddress((void**)&p_xd1, g_xd1);
    cudaGetSymbolAddress((void**)&p_h,   g_h);
    cudaGetSymbolAddress((void**)&p_xs2, g_xs2);
    cudaGetSymbolAddress((void**)&p_xd2, g_xd2);

    // init + CSR build
    zero_kernel<<<256, 256>>>(N);
    hist_kernel<<<(ET + 255) / 256, 256>>>(ei, E, N);
    scan_kernel<<<1, 1024>>>(N);
    scatter_kernel<<<(ET + 255) / 256, 256>>>(ei, E, N);

    const int mblocks = (N + 127) / 128;

    // layer 1 transforms (both in one launch via z)
    {
        dim3 grid(256 / 64, mblocks, 2);
        gemm_tf32_dual<<<grid, 256>>>(x, W_l1, b_l1, p_xs1, W_r1, b_r1, p_xd1,
                                      N, 128, 256);
    }

    // fused layer-1 attention + aggregation (+ bias + relu)
    fused_gat1<<<(N * 32 + 255) / 256, 256>>>(att1, bias1, N);

    // layer 2 transforms
    {
        dim3 grid(1, mblocks, 2);
        gemm_tf32_dual<<<grid, 256>>>(p_h, W_l2, b_l2, p_xs2, W_r2, b_r2, p_xd2,
                                      N, 256, 64);
    }

    // fused layer-2 attention + aggregation + pooling (half-warp per node)
    {
        int warps = (N + 1) / 2;
        fused_gat2<<<(warps * 32 + 255) / 256, 256>>>(att2, bias2, batch, N);
    }

    final_kernel<<<1, 64>>>(W_lin, b_lin, out);
}

// round 6
// speedup vs baseline: 1.0579x; 1.0579x over previous
#include <cuda_runtime.h>
#include <cstdint>
#include <math_constants.h>

// ---------------- problem-size constants ----------------
#define MAXN 50000
#define MAXE 800000
#define MAXET (MAXE + MAXN)   // edges + self loops
#define NG 64                 // graphs

// ---------------- scratch (device globals; allocation-free) ----------------
__device__ float g_xs1[(size_t)MAXN * 256];
__device__ float g_xd1[(size_t)MAXN * 256];
__device__ float g_h  [(size_t)MAXN * 256];
__device__ float g_xs2[(size_t)MAXN * 64];
__device__ float g_xd2[(size_t)MAXN * 64];

__device__ int   g_deg[MAXN];
__device__ int   g_rowptr[MAXN + 1];
__device__ int   g_cursor[MAXN];
__device__ int   g_csr_src[MAXET];

__device__ float g_pool[NG * 64];
__device__ float g_cnt[NG];

__device__ __forceinline__ float lrelu(float v) {
    return v > 0.0f ? v : 0.2f * v;
}

__device__ __forceinline__ unsigned f2tf32(float f) {
    unsigned r;
    asm("cvt.rna.tf32.f32 %0, %1;" : "=r"(r) : "f"(f));
    return r;
}

__device__ __forceinline__ void mma_tf32(float* c, const unsigned* a, const unsigned* b) {
    asm volatile(
        "mma.sync.aligned.m16n8k8.row.col.f32.tf32.tf32.f32 "
        "{%0,%1,%2,%3}, {%4,%5,%6,%7}, {%8,%9}, {%0,%1,%2,%3};"
        : "+f"(c[0]), "+f"(c[1]), "+f"(c[2]), "+f"(c[3])
        : "r"(a[0]), "r"(a[1]), "r"(a[2]), "r"(a[3]), "r"(b[0]), "r"(b[1]));
}

// ---------------- zero / init ----------------
__global__ void zero_kernel(int N) {
    int i = blockIdx.x * blockDim.x + threadIdx.x;
    int stride = gridDim.x * blockDim.x;
    for (int k = i; k < N; k += stride) g_deg[k] = 0;
    if (i < NG * 64) g_pool[i] = 0.0f;
    if (i < NG)      g_cnt[i] = 0.0f;
}

// ---------------- CSR build ----------------
__global__ void hist_kernel(const int* __restrict__ ei, int E, int N) {
    int i = blockIdx.x * blockDim.x + threadIdx.x;
    int ET = E + N;
    if (i >= ET) return;
    int d = (i < E) ? ei[E + i] : (i - E);
    atomicAdd(&g_deg[d], 1);
}

__global__ void scan_kernel(int N) {
    __shared__ int ssum[1024];
    int t = threadIdx.x;
    int chunk = (N + 1023) >> 10;
    int b = t * chunk;
    int e = b + chunk; if (e > N) e = N;
    int s = 0;
    for (int i = b; i < e; i++) s += g_deg[i];
    ssum[t] = s;
    __syncthreads();
    for (int off = 1; off < 1024; off <<= 1) {
        int v = (t >= off) ? ssum[t - off] : 0;
        __syncthreads();
        ssum[t] += v;
        __syncthreads();
    }
    int run = (t == 0) ? 0 : ssum[t - 1];
    for (int i = b; i < e; i++) {
        g_rowptr[i] = run;
        g_cursor[i] = run;
        run += g_deg[i];
    }
    if (t == 1023) g_rowptr[N] = ssum[1023];
}

__global__ void scatter_kernel(const int* __restrict__ ei, int E, int N) {
    int i = blockIdx.x * blockDim.x + threadIdx.x;
    int ET = E + N;
    if (i >= ET) return;
    int s, d;
    if (i < E) { s = ei[i]; d = ei[E + i]; }
    else       { s = i - E; d = s; }
    int pos = atomicAdd(&g_cursor[d], 1);
    g_csr_src[pos] = s;
}

// ---------------- tf32 tensor-core GEMM ----------------
// C[M,Ncol] = A[M,K] @ W[K,Ncol] + bias
// Tile: BM=128, BN=64, BK=32; 256 threads = 8 warps (4m x 2n).
// smem holds PRE-CONVERTED tf32 (unsigned) so the inner loop is pure LDS+MMA.
// blockIdx.z selects (W0,b0,C0) vs (W1,b1,C1).
__global__ void gemm_tf32_dual(const float* __restrict__ A,
                               const float* __restrict__ W0, const float* __restrict__ b0,
                               float* __restrict__ C0,
                               const float* __restrict__ W1, const float* __restrict__ b1,
                               float* __restrict__ C1,
                               int M, int K, int Ncol) {
    const float* W    = blockIdx.z ? W1 : W0;
    const float* bias = blockIdx.z ? b1 : b0;
    float*       C    = blockIdx.z ? C1 : C0;

    __shared__ unsigned As[128][36];   // stride 36: conflict-free frag loads
    __shared__ unsigned Bs[32][68];

    const int t    = threadIdx.x;
    const int lane = t & 31;
    const int warp = t >> 5;
    const int grp  = lane >> 2;   // 0..7
    const int tg   = lane & 3;    // 0..3
    const int warp_m = warp & 3;  // 4 warps along M (32 rows each)
    const int warp_n = warp >> 2; // 2 warps along N (32 cols each)

    const int row0 = blockIdx.y * 128;
    const int col0 = blockIdx.x * 64;

    float acc[2][4][4];
#pragma unroll
    for (int mi = 0; mi < 2; mi++)
#pragma unroll
        for (int ni = 0; ni < 4; ni++)
#pragma unroll
            for (int j = 0; j < 4; j++) acc[mi][ni][j] = 0.0f;

    for (int k0 = 0; k0 < K; k0 += 32) {
        // A tile: 128 rows x 32 cols = 1024 float4 over 256 threads (convert at store)
#pragma unroll
        for (int i = 0; i < 4; i++) {
            int idx = t + i * 256;
            int r  = idx >> 3;
            int c4 = idx & 7;
            int gr = row0 + r;
            float4 v = make_float4(0.f, 0.f, 0.f, 0.f);
            if (gr < M)
                v = *reinterpret_cast<const float4*>(&A[(size_t)gr * K + k0 + c4 * 4]);
            uint4 u = make_uint4(f2tf32(v.x), f2tf32(v.y), f2tf32(v.z), f2tf32(v.w));
            *reinterpret_cast<uint4*>(&As[r][c4 * 4]) = u;
        }
        // B tile: 32 rows x 64 cols = 512 float4
#pragma unroll
        for (int i = 0; i < 2; i++) {
            int idx = t + i * 256;
            int kk = idx >> 4;
            int c4 = idx & 15;
            float4 v = *reinterpret_cast<const float4*>(&W[(size_t)(k0 + kk) * Ncol + col0 + c4 * 4]);
            uint4 u = make_uint4(f2tf32(v.x), f2tf32(v.y), f2tf32(v.z), f2tf32(v.w));
            *reinterpret_cast<uint4*>(&Bs[kk][c4 * 4]) = u;
        }
        __syncthreads();

#pragma unroll
        for (int ks = 0; ks < 32; ks += 8) {
            unsigned af[2][4];
#pragma unroll
            for (int mi = 0; mi < 2; mi++) {
                int r = warp_m * 32 + mi * 16 + grp;
                af[mi][0] = As[r][ks + tg];
                af[mi][1] = As[r + 8][ks + tg];
                af[mi][2] = As[r][ks + tg + 4];
                af[mi][3] = As[r + 8][ks + tg + 4];
            }
            unsigned bf[4][2];
#pragma unroll
            for (int ni = 0; ni < 4; ni++) {
                int c = warp_n * 32 + ni * 8 + grp;
                bf[ni][0] = Bs[ks + tg][c];
                bf[ni][1] = Bs[ks + tg + 4][c];
            }
#pragma unroll
            for (int mi = 0; mi < 2; mi++)
#pragma unroll
                for (int ni = 0; ni < 4; ni++)
                    mma_tf32(acc[mi][ni], af[mi], bf[ni]);
        }
        __syncthreads();
    }

#pragma unroll
    for (int ni = 0; ni < 4; ni++) {
        int gc = col0 + warp_n * 32 + ni * 8 + tg * 2;
        float2 bv = *reinterpret_cast<const float2*>(&bias[gc]);
#pragma unroll
        for (int mi = 0; mi < 2; mi++) {
            int gr = row0 + warp_m * 32 + mi * 16 + grp;
            if (gr < M) {
                float2 o = make_float2(acc[mi][ni][0] + bv.x, acc[mi][ni][1] + bv.y);
                *reinterpret_cast<float2*>(&C[(size_t)gr * Ncol + gc]) = o;
            }
            if (gr + 8 < M) {
                float2 o = make_float2(acc[mi][ni][2] + bv.x, acc[mi][ni][3] + bv.y);
                *reinterpret_cast<float2*>(&C[(size_t)(gr + 8) * Ncol + gc]) = o;
            }
        }
    }
}

// ---------------- fused layer-1 node pass (H=4, C=64) ----------------
// one warp per dst node; online softmax + aggregation; epilogue bias+relu -> g_h
// (round-4 form: single-edge loop — the 2-edge unroll regressed)
__global__ void fused_gat1(const float* __restrict__ att,
                           const float* __restrict__ bias, int N) {
    int warp = (blockIdx.x * blockDim.x + threadIdx.x) >> 5;
    if (warp >= N) return;
    int lane = threadIdx.x & 31;
    int n = warp;
    int c0 = lane * 8;   // 8 channels per lane; lanes 0-7 = head0, etc.

    const float4* xdp = reinterpret_cast<const float4*>(g_xd1 + (size_t)n * 256 + c0);
    float4 d0 = xdp[0], d1 = xdp[1];
    float4 w0 = *reinterpret_cast<const float4*>(att + c0);
    float4 w1 = *reinterpret_cast<const float4*>(att + c0 + 4);

    float m = -CUDART_INF_F, s = 0.0f;
    float acc[8] = {0, 0, 0, 0, 0, 0, 0, 0};

    int beg = g_rowptr[n], end = g_rowptr[n + 1];
    for (int e = beg; e < end; e++) {
        int src = g_csr_src[e];
        const float4* xsp = reinterpret_cast<const float4*>(g_xs1 + (size_t)src * 256 + c0);
        float4 a0 = xsp[0], a1 = xsp[1];

        float p = lrelu(a0.x + d0.x) * w0.x + lrelu(a0.y + d0.y) * w0.y
                + lrelu(a0.z + d0.z) * w0.z + lrelu(a0.w + d0.w) * w0.w
                + lrelu(a1.x + d1.x) * w1.x + lrelu(a1.y + d1.y) * w1.y
                + lrelu(a1.z + d1.z) * w1.z + lrelu(a1.w + d1.w) * w1.w;
        p += __shfl_xor_sync(0xffffffffu, p, 4);
        p += __shfl_xor_sync(0xffffffffu, p, 2);
        p += __shfl_xor_sync(0xffffffffu, p, 1);

        float m_new = fmaxf(m, p);
        float scale = __expf(m - m_new);
        float ex    = __expf(p - m_new);
        s = s * scale + ex;
        acc[0] = acc[0] * scale + ex * a0.x;
        acc[1] = acc[1] * scale + ex * a0.y;
        acc[2] = acc[2] * scale + ex * a0.z;
        acc[3] = acc[3] * scale + ex * a0.w;
        acc[4] = acc[4] * scale + ex * a1.x;
        acc[5] = acc[5] * scale + ex * a1.y;
        acc[6] = acc[6] * scale + ex * a1.z;
        acc[7] = acc[7] * scale + ex * a1.w;
        m = m_new;
    }

    float inv = 1.0f / s;
    float4 b0 = *reinterpret_cast<const float4*>(bias + c0);
    float4 b1 = *reinterpret_cast<const float4*>(bias + c0 + 4);
    float4 o0, o1;
    o0.x = fmaxf(acc[0] * inv + b0.x, 0.0f);
    o0.y = fmaxf(acc[1] * inv + b0.y, 0.0f);
    o0.z = fmaxf(acc[2] * inv + b0.z, 0.0f);
    o0.w = fmaxf(acc[3] * inv + b0.w, 0.0f);
    o1.x = fmaxf(acc[4] * inv + b1.x, 0.0f);
    o1.y = fmaxf(acc[5] * inv + b1.y, 0.0f);
    o1.z = fmaxf(acc[6] * inv + b1.z, 0.0f);
    o1.w = fmaxf(acc[7] * inv + b1.w, 0.0f);
    float4* hp = reinterpret_cast<float4*>(g_h + (size_t)n * 256 + c0);
    hp[0] = o0;
    hp[1] = o1;
}

// ---------------- fused layer-2 node pass (H=1, C=64) + pool ----------------
// (round-4 form: full warp per node, float2 per lane — half-warp variant regressed)
__global__ void fused_gat2(const float* __restrict__ att,
                           const float* __restrict__ bias,
                           const int* __restrict__ batch, int N) {
    int warp = (blockIdx.x * blockDim.x + threadIdx.x) >> 5;
    if (warp >= N) return;
    int lane = threadIdx.x & 31;
    int n = warp;
    int c0 = lane * 2;

    float2 d = *reinterpret_cast<const float2*>(g_xd2 + (size_t)n * 64 + c0);
    float2 w = *reinterpret_cast<const float2*>(att + c0);

    float m = -CUDART_INF_F, s = 0.0f;
    float acc0 = 0.0f, acc1 = 0.0f;

    int beg = g_rowptr[n], end = g_rowptr[n + 1];
    for (int e = beg; e < end; e++) {
        int src = g_csr_src[e];
        float2 a = *reinterpret_cast<const float2*>(g_xs2 + (size_t)src * 64 + c0);
        float p = lrelu(a.x + d.x) * w.x + lrelu(a.y + d.y) * w.y;
        p += __shfl_xor_sync(0xffffffffu, p, 16);
        p += __shfl_xor_sync(0xffffffffu, p, 8);
        p += __shfl_xor_sync(0xffffffffu, p, 4);
        p += __shfl_xor_sync(0xffffffffu, p, 2);
        p += __shfl_xor_sync(0xffffffffu, p, 1);

        float m_new = fmaxf(m, p);
        float scale = __expf(m - m_new);
        float ex    = __expf(p - m_new);
        s = s * scale + ex;
        acc0 = acc0 * scale + ex * a.x;
        acc1 = acc1 * scale + ex * a.y;
        m = m_new;
    }

    float inv = 1.0f / s;
    float v0 = acc0 * inv + bias[c0];
    float v1 = acc1 * inv + bias[c0 + 1];

    int g = batch[n];
    atomicAdd(&g_pool[g * 64 + c0], v0);
    atomicAdd(&g_pool[g * 64 + c0 + 1], v1);
    if (lane == 0) atomicAdd(&g_cnt[g], 1.0f);
}

__global__ void final_kernel(const float* __restrict__ Wlin,
                             const float* __restrict__ blin,
                             float* __restrict__ out) {
    int g = threadIdx.x;
    if (g >= NG) return;
    float cnt = g_cnt[g];
    if (cnt < 1.0f) cnt = 1.0f;
    float sum = 0.0f;
#pragma unroll
    for (int c = 0; c < 64; c++)
        sum += (g_pool[g * 64 + c] / cnt) * Wlin[c];
    out[g] = sum + blin[0];
}

// ---------------- launcher ----------------
extern "C" void kernel_launch(void* const* d_in, const int* in_sizes, int n_in,
                              void* d_out, int out_size) {
    const float* x      = (const float*)d_in[0];
    const int*   ei     = (const int*)d_in[1];
    const int*   batch  = (const int*)d_in[2];
    const float* W_l1   = (const float*)d_in[3];
    const float* b_l1   = (const float*)d_in[4];
    const float* W_r1   = (const float*)d_in[5];
    const float* b_r1   = (const float*)d_in[6];
    const float* att1   = (const float*)d_in[7];
    const float* bias1  = (const float*)d_in[8];
    const float* W_l2   = (const float*)d_in[9];
    const float* b_l2   = (const float*)d_in[10];
    const float* W_r2   = (const float*)d_in[11];
    const float* b_r2   = (const float*)d_in[12];
    const float* att2   = (const float*)d_in[13];
    const float* bias2  = (const float*)d_in[14];
    const float* W_lin  = (const float*)d_in[15];
    const float* b_lin  = (const float*)d_in[16];
    float* out = (float*)d_out;

    const int N = in_sizes[0] / 128;   // 50000
    const int E = in_sizes[1] / 2;     // 800000
    const int ET = E + N;

    // __device__ symbols -> real device pointers (host-side query; capture-safe)
    float *p_xs1, *p_xd1, *p_h, *p_xs2, *p_xd2;
    cudaGetSymbolAddress((void**)&p_xs1, g_xs1);
    cudaGetSymbolAddress((void**)&p_xd1, g_xd1);
    cudaGetSymbolAddress((void**)&p_h,   g_h);
    cudaGetSymbolAddress((void**)&p_xs2, g_xs2);
    cudaGetSymbolAddress((void**)&p_xd2, g_xd2);

    // init + CSR build
    zero_kernel<<<256, 256>>>(N);
    hist_kernel<<<(ET + 255) / 256, 256>>>(ei, E, N);
    scan_kernel<<<1, 1024>>>(N);
    scatter_kernel<<<(ET + 255) / 256, 256>>>(ei, E, N);

    const int mblocks = (N + 127) / 128;

    // layer 1 transforms (both in one launch via z)
    {
        dim3 grid(256 / 64, mblocks, 2);
        gemm_tf32_dual<<<grid, 256>>>(x, W_l1, b_l1, p_xs1, W_r1, b_r1, p_xd1,
                                      N, 128, 256);
    }

    // fused layer-1 attention + aggregation (+ bias + relu)
    fused_gat1<<<(N * 32 + 255) / 256, 256>>>(att1, bias1, N);

    // layer 2 transforms
    {
        dim3 grid(1, mblocks, 2);
        gemm_tf32_dual<<<grid, 256>>>(p_h, W_l2, b_l2, p_xs2, W_r2, b_r2, p_xd2,
                                      N, 256, 64);
    }

    // fused layer-2 attention + aggregation + pooling
    fused_gat2<<<(N * 32 + 255) / 256, 256>>>(att2, bias2, batch, N);

    final_kernel<<<1, 64>>>(W_lin, b_lin, out);
}

// round 7
// speedup vs baseline: 1.0683x; 1.0098x over previous
#include <cuda_runtime.h>
#include <cuda_fp16.h>
#include <cstdint>
#include <math_constants.h>

// ---------------- problem-size constants ----------------
#define MAXN 50000
#define MAXE 800000
#define MAXET (MAXE + MAXN)   // edges + self loops
#define NG 64                 // graphs

// ---------------- scratch (device globals; allocation-free) ----------------
__device__ __half g_xs1h[(size_t)MAXN * 256];   // fp16 gathered operand, layer 1
__device__ float  g_xd1[(size_t)MAXN * 256];
__device__ float  g_h  [(size_t)MAXN * 256];
__device__ __half g_xs2h[(size_t)MAXN * 64];    // fp16 gathered operand, layer 2
__device__ float  g_xd2[(size_t)MAXN * 64];

__device__ int   g_deg[MAXN];
__device__ int   g_rowptr[MAXN + 1];
__device__ int   g_cursor[MAXN];
__device__ int   g_csr_src[MAXET];

__device__ float g_pool[NG * 64];
__device__ float g_cnt[NG];

__device__ __forceinline__ float lrelu(float v) {
    return v > 0.0f ? v : 0.2f * v;
}

__device__ __forceinline__ unsigned f2tf32(float f) {
    unsigned r;
    asm("cvt.rna.tf32.f32 %0, %1;" : "=r"(r) : "f"(f));
    return r;
}

__device__ __forceinline__ void mma_tf32(float* c, const unsigned* a, const unsigned* b) {
    asm volatile(
        "mma.sync.aligned.m16n8k8.row.col.f32.tf32.tf32.f32 "
        "{%0,%1,%2,%3}, {%4,%5,%6,%7}, {%8,%9}, {%0,%1,%2,%3};"
        : "+f"(c[0]), "+f"(c[1]), "+f"(c[2]), "+f"(c[3])
        : "r"(a[0]), "r"(a[1]), "r"(a[2]), "r"(a[3]), "r"(b[0]), "r"(b[1]));
}

// ---------------- zero / init ----------------
__global__ void zero_kernel(int N) {
    int i = blockIdx.x * blockDim.x + threadIdx.x;
    int stride = gridDim.x * blockDim.x;
    for (int k = i; k < N; k += stride) g_deg[k] = 0;
    if (i < NG * 64) g_pool[i] = 0.0f;
    if (i < NG)      g_cnt[i] = 0.0f;
}

// ---------------- CSR build ----------------
__global__ void hist_kernel(const int* __restrict__ ei, int E, int N) {
    int i = blockIdx.x * blockDim.x + threadIdx.x;
    int ET = E + N;
    if (i >= ET) return;
    int d = (i < E) ? ei[E + i] : (i - E);
    atomicAdd(&g_deg[d], 1);
}

__global__ void scan_kernel(int N) {
    __shared__ int ssum[1024];
    int t = threadIdx.x;
    int chunk = (N + 1023) >> 10;
    int b = t * chunk;
    int e = b + chunk; if (e > N) e = N;
    int s = 0;
    for (int i = b; i < e; i++) s += g_deg[i];
    ssum[t] = s;
    __syncthreads();
    for (int off = 1; off < 1024; off <<= 1) {
        int v = (t >= off) ? ssum[t - off] : 0;
        __syncthreads();
        ssum[t] += v;
        __syncthreads();
    }
    int run = (t == 0) ? 0 : ssum[t - 1];
    for (int i = b; i < e; i++) {
        g_rowptr[i] = run;
        g_cursor[i] = run;
        run += g_deg[i];
    }
    if (t == 1023) g_rowptr[N] = ssum[1023];
}

__global__ void scatter_kernel(const int* __restrict__ ei, int E, int N) {
    int i = blockIdx.x * blockDim.x + threadIdx.x;
    int ET = E + N;
    if (i >= ET) return;
    int s, d;
    if (i < E) { s = ei[i]; d = ei[E + i]; }
    else       { s = i - E; d = s; }
    int pos = atomicAdd(&g_cursor[d], 1);
    g_csr_src[pos] = s;
}

// ---------------- tf32 tensor-core GEMM ----------------
// C[M,Ncol] = A[M,K] @ W[K,Ncol] + bias
// Tile: BM=128, BN=64, BK=32; 256 threads = 8 warps (4m x 2n).
// smem holds PRE-CONVERTED tf32. blockIdx.z==0 writes HALF output (xs path),
// blockIdx.z==1 writes FLOAT output (xd path).
__global__ void gemm_tf32_dual(const float* __restrict__ A,
                               const float* __restrict__ W0, const float* __restrict__ b0,
                               __half* __restrict__ C0h,
                               const float* __restrict__ W1, const float* __restrict__ b1,
                               float* __restrict__ C1,
                               int M, int K, int Ncol) {
    const float* W    = blockIdx.z ? W1 : W0;
    const float* bias = blockIdx.z ? b1 : b0;

    __shared__ unsigned As[128][36];
    __shared__ unsigned Bs[32][68];

    const int t    = threadIdx.x;
    const int lane = t & 31;
    const int warp = t >> 5;
    const int grp  = lane >> 2;
    const int tg   = lane & 3;
    const int warp_m = warp & 3;
    const int warp_n = warp >> 2;

    const int row0 = blockIdx.y * 128;
    const int col0 = blockIdx.x * 64;

    float acc[2][4][4];
#pragma unroll
    for (int mi = 0; mi < 2; mi++)
#pragma unroll
        for (int ni = 0; ni < 4; ni++)
#pragma unroll
            for (int j = 0; j < 4; j++) acc[mi][ni][j] = 0.0f;

    for (int k0 = 0; k0 < K; k0 += 32) {
#pragma unroll
        for (int i = 0; i < 4; i++) {
            int idx = t + i * 256;
            int r  = idx >> 3;
            int c4 = idx & 7;
            int gr = row0 + r;
            float4 v = make_float4(0.f, 0.f, 0.f, 0.f);
            if (gr < M)
                v = *reinterpret_cast<const float4*>(&A[(size_t)gr * K + k0 + c4 * 4]);
            uint4 u = make_uint4(f2tf32(v.x), f2tf32(v.y), f2tf32(v.z), f2tf32(v.w));
            *reinterpret_cast<uint4*>(&As[r][c4 * 4]) = u;
        }
#pragma unroll
        for (int i = 0; i < 2; i++) {
            int idx = t + i * 256;
            int kk = idx >> 4;
            int c4 = idx & 15;
            float4 v = *reinterpret_cast<const float4*>(&W[(size_t)(k0 + kk) * Ncol + col0 + c4 * 4]);
            uint4 u = make_uint4(f2tf32(v.x), f2tf32(v.y), f2tf32(v.z), f2tf32(v.w));
            *reinterpret_cast<uint4*>(&Bs[kk][c4 * 4]) = u;
        }
        __syncthreads();

#pragma unroll
        for (int ks = 0; ks < 32; ks += 8) {
            unsigned af[2][4];
#pragma unroll
            for (int mi = 0; mi < 2; mi++) {
                int r = warp_m * 32 + mi * 16 + grp;
                af[mi][0] = As[r][ks + tg];
                af[mi][1] = As[r + 8][ks + tg];
                af[mi][2] = As[r][ks + tg + 4];
                af[mi][3] = As[r + 8][ks + tg + 4];
            }
            unsigned bf[4][2];
#pragma unroll
            for (int ni = 0; ni < 4; ni++) {
                int c = warp_n * 32 + ni * 8 + grp;
                bf[ni][0] = Bs[ks + tg][c];
                bf[ni][1] = Bs[ks + tg + 4][c];
            }
#pragma unroll
            for (int mi = 0; mi < 2; mi++)
#pragma unroll
                for (int ni = 0; ni < 4; ni++)
                    mma_tf32(acc[mi][ni], af[mi], bf[ni]);
        }
        __syncthreads();
    }

    const bool half_out = (blockIdx.z == 0);
#pragma unroll
    for (int ni = 0; ni < 4; ni++) {
        int gc = col0 + warp_n * 32 + ni * 8 + tg * 2;
        float2 bv = *reinterpret_cast<const float2*>(&bias[gc]);
#pragma unroll
        for (int mi = 0; mi < 2; mi++) {
            int gr = row0 + warp_m * 32 + mi * 16 + grp;
            if (gr < M) {
                float ox = acc[mi][ni][0] + bv.x;
                float oy = acc[mi][ni][1] + bv.y;
                if (half_out)
                    *reinterpret_cast<__half2*>(&C0h[(size_t)gr * Ncol + gc]) =
                        __floats2half2_rn(ox, oy);
                else
                    *reinterpret_cast<float2*>(&C1[(size_t)gr * Ncol + gc]) =
                        make_float2(ox, oy);
            }
            if (gr + 8 < M) {
                float ox = acc[mi][ni][2] + bv.x;
                float oy = acc[mi][ni][3] + bv.y;
                if (half_out)
                    *reinterpret_cast<__half2*>(&C0h[(size_t)(gr + 8) * Ncol + gc]) =
                        __floats2half2_rn(ox, oy);
                else
                    *reinterpret_cast<float2*>(&C1[(size_t)(gr + 8) * Ncol + gc]) =
                        make_float2(ox, oy);
            }
        }
    }
}

// ---------------- fused layer-1 node pass (H=4, C=64) ----------------
// one warp per dst node; online softmax + aggregation; epilogue bias+relu -> g_h
// xs gathered in fp16 (16B per lane per edge).
__global__ void fused_gat1(const float* __restrict__ att,
                           const float* __restrict__ bias, int N) {
    int warp = (blockIdx.x * blockDim.x + threadIdx.x) >> 5;
    if (warp >= N) return;
    int lane = threadIdx.x & 31;
    int n = warp;
    int c0 = lane * 8;

    const float4* xdp = reinterpret_cast<const float4*>(g_xd1 + (size_t)n * 256 + c0);
    float4 d0 = xdp[0], d1 = xdp[1];
    float4 w0 = *reinterpret_cast<const float4*>(att + c0);
    float4 w1 = *reinterpret_cast<const float4*>(att + c0 + 4);

    float m = -CUDART_INF_F, s = 0.0f;
    float acc[8] = {0, 0, 0, 0, 0, 0, 0, 0};

    int beg = g_rowptr[n], end = g_rowptr[n + 1];
    for (int e = beg; e < end; e++) {
        int src = g_csr_src[e];
        uint4 raw = *reinterpret_cast<const uint4*>(g_xs1h + (size_t)src * 256 + c0);
        float2 f0 = __half22float2(*reinterpret_cast<__half2*>(&raw.x));
        float2 f1 = __half22float2(*reinterpret_cast<__half2*>(&raw.y));
        float2 f2 = __half22float2(*reinterpret_cast<__half2*>(&raw.z));
        float2 f3 = __half22float2(*reinterpret_cast<__half2*>(&raw.w));

        float p = lrelu(f0.x + d0.x) * w0.x + lrelu(f0.y + d0.y) * w0.y
                + lrelu(f1.x + d0.z) * w0.z + lrelu(f1.y + d0.w) * w0.w
                + lrelu(f2.x + d1.x) * w1.x + lrelu(f2.y + d1.y) * w1.y
                + lrelu(f3.x + d1.z) * w1.z + lrelu(f3.y + d1.w) * w1.w;
        p += __shfl_xor_sync(0xffffffffu, p, 4);
        p += __shfl_xor_sync(0xffffffffu, p, 2);
        p += __shfl_xor_sync(0xffffffffu, p, 1);

        float m_new = fmaxf(m, p);
        float scale = __expf(m - m_new);
        float ex    = __expf(p - m_new);
        s = s * scale + ex;
        acc[0] = acc[0] * scale + ex * f0.x;
        acc[1] = acc[1] * scale + ex * f0.y;
        acc[2] = acc[2] * scale + ex * f1.x;
        acc[3] = acc[3] * scale + ex * f1.y;
        acc[4] = acc[4] * scale + ex * f2.x;
        acc[5] = acc[5] * scale + ex * f2.y;
        acc[6] = acc[6] * scale + ex * f3.x;
        acc[7] = acc[7] * scale + ex * f3.y;
        m = m_new;
    }

    float inv = 1.0f / s;
    float4 b0 = *reinterpret_cast<const float4*>(bias + c0);
    float4 b1 = *reinterpret_cast<const float4*>(bias + c0 + 4);
    float4 o0, o1;
    o0.x = fmaxf(acc[0] * inv + b0.x, 0.0f);
    o0.y = fmaxf(acc[1] * inv + b0.y, 0.0f);
    o0.z = fmaxf(acc[2] * inv + b0.z, 0.0f);
    o0.w = fmaxf(acc[3] * inv + b0.w, 0.0f);
    o1.x = fmaxf(acc[4] * inv + b1.x, 0.0f);
    o1.y = fmaxf(acc[5] * inv + b1.y, 0.0f);
    o1.z = fmaxf(acc[6] * inv + b1.z, 0.0f);
    o1.w = fmaxf(acc[7] * inv + b1.w, 0.0f);
    float4* hp = reinterpret_cast<float4*>(g_h + (size_t)n * 256 + c0);
    hp[0] = o0;
    hp[1] = o1;
}

// ---------------- fused layer-2 node pass (H=1, C=64) + pool ----------------
__global__ void fused_gat2(const float* __restrict__ att,
                           const float* __restrict__ bias,
                           const int* __restrict__ batch, int N) {
    int warp = (blockIdx.x * blockDim.x + threadIdx.x) >> 5;
    if (warp >= N) return;
    int lane = threadIdx.x & 31;
    int n = warp;
    int c0 = lane * 2;

    float2 d = *reinterpret_cast<const float2*>(g_xd2 + (size_t)n * 64 + c0);
    float2 w = *reinterpret_cast<const float2*>(att + c0);

    float m = -CUDART_INF_F, s = 0.0f;
    float acc0 = 0.0f, acc1 = 0.0f;

    int beg = g_rowptr[n], end = g_rowptr[n + 1];
    for (int e = beg; e < end; e++) {
        int src = g_csr_src[e];
        float2 a = __half22float2(
            *reinterpret_cast<const __half2*>(g_xs2h + (size_t)src * 64 + c0));
        float p = lrelu(a.x + d.x) * w.x + lrelu(a.y + d.y) * w.y;
        p += __shfl_xor_sync(0xffffffffu, p, 16);
        p += __shfl_xor_sync(0xffffffffu, p, 8);
        p += __shfl_xor_sync(0xffffffffu, p, 4);
        p += __shfl_xor_sync(0xffffffffu, p, 2);
        p += __shfl_xor_sync(0xffffffffu, p, 1);

        float m_new = fmaxf(m, p);
        float scale = __expf(m - m_new);
        float ex    = __expf(p - m_new);
        s = s * scale + ex;
        acc0 = acc0 * scale + ex * a.x;
        acc1 = acc1 * scale + ex * a.y;
        m = m_new;
    }

    float inv = 1.0f / s;
    float v0 = acc0 * inv + bias[c0];
    float v1 = acc1 * inv + bias[c0 + 1];

    int g = batch[n];
    atomicAdd(&g_pool[g * 64 + c0], v0);
    atomicAdd(&g_pool[g * 64 + c0 + 1], v1);
    if (lane == 0) atomicAdd(&g_cnt[g], 1.0f);
}

__global__ void final_kernel(const float* __restrict__ Wlin,
                             const float* __restrict__ blin,
                             float* __restrict__ out) {
    int g = threadIdx.x;
    if (g >= NG) return;
    float cnt = g_cnt[g];
    if (cnt < 1.0f) cnt = 1.0f;
    float sum = 0.0f;
#pragma unroll
    for (int c = 0; c < 64; c++)
        sum += (g_pool[g * 64 + c] / cnt) * Wlin[c];
    out[g] = sum + blin[0];
}

// ---------------- launcher ----------------
extern "C" void kernel_launch(void* const* d_in, const int* in_sizes, int n_in,
                              void* d_out, int out_size) {
    const float* x      = (const float*)d_in[0];
    const int*   ei     = (const int*)d_in[1];
    const int*   batch  = (const int*)d_in[2];
    const float* W_l1   = (const float*)d_in[3];
    const float* b_l1   = (const float*)d_in[4];
    const float* W_r1   = (const float*)d_in[5];
    const float* b_r1   = (const float*)d_in[6];
    const float* att1   = (const float*)d_in[7];
    const float* bias1  = (const float*)d_in[8];
    const float* W_l2   = (const float*)d_in[9];
    const float* b_l2   = (const float*)d_in[10];
    const float* W_r2   = (const float*)d_in[11];
    const float* b_r2   = (const float*)d_in[12];
    const float* att2   = (const float*)d_in[13];
    const float* bias2  = (const float*)d_in[14];
    const float* W_lin  = (const float*)d_in[15];
    const float* b_lin  = (const float*)d_in[16];
    float* out = (float*)d_out;

    const int N = in_sizes[0] / 128;   // 50000
    const int E = in_sizes[1] / 2;     // 800000
    const int ET = E + N;

    // __device__ symbols -> real device pointers (host-side query; capture-safe)
    __half *p_xs1h, *p_xs2h;
    float *p_xd1, *p_h, *p_xd2;
    cudaGetSymbolAddress((void**)&p_xs1h, g_xs1h);
    cudaGetSymbolAddress((void**)&p_xd1,  g_xd1);
    cudaGetSymbolAddress((void**)&p_h,    g_h);
    cudaGetSymbolAddress((void**)&p_xs2h, g_xs2h);
    cudaGetSymbolAddress((void**)&p_xd2,  g_xd2);

    // init + CSR build
    zero_kernel<<<256, 256>>>(N);
    hist_kernel<<<(ET + 255) / 256, 256>>>(ei, E, N);
    scan_kernel<<<1, 1024>>>(N);
    scatter_kernel<<<(ET + 255) / 256, 256>>>(ei, E, N);

    const int mblocks = (N + 127) / 128;

    // layer 1 transforms (z=0 -> half xs1, z=1 -> float xd1)
    {
        dim3 grid(256 / 64, mblocks, 2);
        gemm_tf32_dual<<<grid, 256>>>(x, W_l1, b_l1, p_xs1h, W_r1, b_r1, p_xd1,
                                      N, 128, 256);
    }

    // fused layer-1 attention + aggregation (+ bias + relu)
    fused_gat1<<<(N * 32 + 255) / 256, 256>>>(att1, bias1, N);

    // layer 2 transforms (z=0 -> half xs2, z=1 -> float xd2)
    {
        dim3 grid(1, mblocks, 2);
        gemm_tf32_dual<<<grid, 256>>>(p_h, W_l2, b_l2, p_xs2h, W_r2, b_r2, p_xd2,
                                      N, 256, 64);
    }

    // fused layer-2 attention + aggregation + pooling
    fused_gat2<<<(N * 32 + 255) / 256, 256>>>(att2, bias2, batch, N);

    final_kernel<<<1, 64>>>(W_lin, b_lin, out);
}

// round 8
// speedup vs baseline: 1.0958x; 1.0258x over previous
#include <cuda_runtime.h>
#include <cuda_fp16.h>
#include <cstdint>
#include <math_constants.h>

// ---------------- problem-size constants ----------------
#define MAXN 50000
#define MAXE 800000
#define MAXET (MAXE + MAXN)   // edges + self loops
#define NG 64                 // graphs

// ---------------- scratch (device globals; allocation-free) ----------------
__device__ __align__(16) __half g_xh  [(size_t)MAXN * 128];  // fp16 copy of x
__device__ __align__(16) __half g_xs1h[(size_t)MAXN * 256];  // fp16 xs, layer 1
__device__ __align__(16) float  g_xd1 [(size_t)MAXN * 256];
__device__ __align__(16) __half g_hh  [(size_t)MAXN * 256];  // fp16 h (layer-1 out)
__device__ __align__(16) __half g_xs2h[(size_t)MAXN * 64];   // fp16 xs, layer 2
__device__ __align__(16) float  g_xd2 [(size_t)MAXN * 64];

__device__ int   g_deg[MAXN];
__device__ int   g_rowptr[MAXN + 1];
__device__ int   g_cursor[MAXN];
__device__ int   g_csr_src[MAXET];

__device__ float g_pool[NG * 64];
__device__ float g_cnt[NG];

__device__ __forceinline__ float lrelu(float v) {
    return v > 0.0f ? v : 0.2f * v;
}

// fp16 mma: D(f32) += A(f16) * B(f16), 16x8x16
__device__ __forceinline__ void mma_f16(float* c, const unsigned* a, const unsigned* b) {
    asm volatile(
        "mma.sync.aligned.m16n8k16.row.col.f32.f16.f16.f32 "
        "{%0,%1,%2,%3}, {%4,%5,%6,%7}, {%8,%9}, {%0,%1,%2,%3};"
        : "+f"(c[0]), "+f"(c[1]), "+f"(c[2]), "+f"(c[3])
        : "r"(a[0]), "r"(a[1]), "r"(a[2]), "r"(a[3]), "r"(b[0]), "r"(b[1]));
}

// ---------------- zero / init ----------------
__global__ void zero_kernel(int N) {
    int i = blockIdx.x * blockDim.x + threadIdx.x;
    int stride = gridDim.x * blockDim.x;
    for (int k = i; k < N; k += stride) g_deg[k] = 0;
    if (i < NG * 64) g_pool[i] = 0.0f;
    if (i < NG)      g_cnt[i] = 0.0f;
}

// fp32 -> fp16 convert (x), 4 elems/thread
__global__ void f2h_kernel(const float* __restrict__ in, size_t total4) {
    size_t i = (size_t)blockIdx.x * blockDim.x + threadIdx.x;
    size_t stride = (size_t)gridDim.x * blockDim.x;
    for (; i < total4; i += stride) {
        float4 v = reinterpret_cast<const float4*>(in)[i];
        __half2 h0 = __floats2half2_rn(v.x, v.y);
        __half2 h1 = __floats2half2_rn(v.z, v.w);
        reinterpret_cast<uint2*>(g_xh)[i] =
            make_uint2(*reinterpret_cast<unsigned*>(&h0), *reinterpret_cast<unsigned*>(&h1));
    }
}

// ---------------- CSR build ----------------
__global__ void hist_kernel(const int* __restrict__ ei, int E, int N) {
    int i = blockIdx.x * blockDim.x + threadIdx.x;
    int ET = E + N;
    if (i >= ET) return;
    int d = (i < E) ? ei[E + i] : (i - E);
    atomicAdd(&g_deg[d], 1);
}

__global__ void scan_kernel(int N) {
    __shared__ int ssum[1024];
    int t = threadIdx.x;
    int chunk = (N + 1023) >> 10;
    int b = t * chunk;
    int e = b + chunk; if (e > N) e = N;
    int s = 0;
    for (int i = b; i < e; i++) s += g_deg[i];
    ssum[t] = s;
    __syncthreads();
    for (int off = 1; off < 1024; off <<= 1) {
        int v = (t >= off) ? ssum[t - off] : 0;
        __syncthreads();
        ssum[t] += v;
        __syncthreads();
    }
    int run = (t == 0) ? 0 : ssum[t - 1];
    for (int i = b; i < e; i++) {
        g_rowptr[i] = run;
        g_cursor[i] = run;
        run += g_deg[i];
    }
    if (t == 1023) g_rowptr[N] = ssum[1023];
}

__global__ void scatter_kernel(const int* __restrict__ ei, int E, int N) {
    int i = blockIdx.x * blockDim.x + threadIdx.x;
    int ET = E + N;
    if (i >= ET) return;
    int s, d;
    if (i < E) { s = ei[i]; d = ei[E + i]; }
    else       { s = i - E; d = s; }
    int pos = atomicAdd(&g_cursor[d], 1);
    g_csr_src[pos] = s;
}

// ---------------- fp16 tensor-core GEMM ----------------
// C[M,Ncol] = A[M,K](f16) @ W[K,Ncol](f32->f16) + bias
// Tile: BM=128, BN=64, BK=32; 256 threads = 8 warps (4m x 2n), m16n8k16.
// blockIdx.z==0 -> HALF output (xs), z==1 -> FLOAT output (xd).
__global__ void gemm_f16_dual(const __half* __restrict__ A,
                              const float* __restrict__ W0, const float* __restrict__ b0,
                              __half* __restrict__ C0h,
                              const float* __restrict__ W1, const float* __restrict__ b1,
                              float* __restrict__ C1,
                              int M, int K, int Ncol) {
    const float* W    = blockIdx.z ? W1 : W0;
    const float* bias = blockIdx.z ? b1 : b0;

    __shared__ __half As[128][40];   // row-major [m][k], pad 40 -> conflict-free frags
    __shared__ __half Bs[64][40];    // n-major  [n][k]

    const int t    = threadIdx.x;
    const int lane = t & 31;
    const int warp = t >> 5;
    const int grp  = lane >> 2;   // 0..7
    const int tg   = lane & 3;    // 0..3
    const int warp_m = warp & 3;  // 4 warps along M (32 rows)
    const int warp_n = warp >> 2; // 2 warps along N (32 cols)

    const int row0 = blockIdx.y * 128;
    const int col0 = blockIdx.x * 64;

    float acc[2][4][4];
#pragma unroll
    for (int mi = 0; mi < 2; mi++)
#pragma unroll
        for (int ni = 0; ni < 4; ni++)
#pragma unroll
            for (int j = 0; j < 4; j++) acc[mi][ni][j] = 0.0f;

    for (int k0 = 0; k0 < K; k0 += 32) {
        // A tile: 128 x 32 halves = 512 uint4 over 256 threads (fp16 global)
#pragma unroll
        for (int i = 0; i < 2; i++) {
            int idx = t + i * 256;
            int r  = idx >> 2;       // 0..127
            int c8 = idx & 3;        // 8-half chunk
            int gr = row0 + r;
            uint4 v = make_uint4(0u, 0u, 0u, 0u);
            if (gr < M)
                v = *reinterpret_cast<const uint4*>(&A[(size_t)gr * K + k0 + c8 * 8]);
            *reinterpret_cast<uint4*>(&As[r][c8 * 8]) = v;
        }
        // B tile: W[k0..k0+32][col0..col0+64] fp32, store transposed n-major as fp16
#pragma unroll
        for (int i = 0; i < 2; i++) {
            int idx = t + i * 256;
            int kk = idx >> 4;       // 0..31
            int c4 = idx & 15;       // 4-col group
            float4 v = *reinterpret_cast<const float4*>(&W[(size_t)(k0 + kk) * Ncol + col0 + c4 * 4]);
            int c = c4 * 4;
            Bs[c + 0][kk] = __float2half_rn(v.x);
            Bs[c + 1][kk] = __float2half_rn(v.y);
            Bs[c + 2][kk] = __float2half_rn(v.z);
            Bs[c + 3][kk] = __float2half_rn(v.w);
        }
        __syncthreads();

#pragma unroll
        for (int ks = 0; ks < 32; ks += 16) {
            unsigned af[2][4];
#pragma unroll
            for (int mi = 0; mi < 2; mi++) {
                int r = warp_m * 32 + mi * 16 + grp;
                af[mi][0] = *reinterpret_cast<const unsigned*>(&As[r][ks + 2 * tg]);
                af[mi][1] = *reinterpret_cast<const unsigned*>(&As[r + 8][ks + 2 * tg]);
                af[mi][2] = *reinterpret_cast<const unsigned*>(&As[r][ks + 2 * tg + 8]);
                af[mi][3] = *reinterpret_cast<const unsigned*>(&As[r + 8][ks + 2 * tg + 8]);
            }
            unsigned bf[4][2];
#pragma unroll
            for (int ni = 0; ni < 4; ni++) {
                int c = warp_n * 32 + ni * 8 + grp;
                bf[ni][0] = *reinterpret_cast<const unsigned*>(&Bs[c][ks + 2 * tg]);
                bf[ni][1] = *reinterpret_cast<const unsigned*>(&Bs[c][ks + 2 * tg + 8]);
            }
#pragma unroll
            for (int mi = 0; mi < 2; mi++)
#pragma unroll
                for (int ni = 0; ni < 4; ni++)
                    mma_f16(acc[mi][ni], af[mi], bf[ni]);
        }
        __syncthreads();
    }

    const bool half_out = (blockIdx.z == 0);
#pragma unroll
    for (int ni = 0; ni < 4; ni++) {
        int gc = col0 + warp_n * 32 + ni * 8 + tg * 2;
        float2 bv = *reinterpret_cast<const float2*>(&bias[gc]);
#pragma unroll
        for (int mi = 0; mi < 2; mi++) {
            int gr = row0 + warp_m * 32 + mi * 16 + grp;
            if (gr < M) {
                float ox = acc[mi][ni][0] + bv.x;
                float oy = acc[mi][ni][1] + bv.y;
                if (half_out)
                    *reinterpret_cast<__half2*>(&C0h[(size_t)gr * Ncol + gc]) =
                        __floats2half2_rn(ox, oy);
                else
                    *reinterpret_cast<float2*>(&C1[(size_t)gr * Ncol + gc]) =
                        make_float2(ox, oy);
            }
            if (gr + 8 < M) {
                float ox = acc[mi][ni][2] + bv.x;
                float oy = acc[mi][ni][3] + bv.y;
                if (half_out)
                    *reinterpret_cast<__half2*>(&C0h[(size_t)(gr + 8) * Ncol + gc]) =
                        __floats2half2_rn(ox, oy);
                else
                    *reinterpret_cast<float2*>(&C1[(size_t)(gr + 8) * Ncol + gc]) =
                        make_float2(ox, oy);
            }
        }
    }
}

// ---------------- fused layer-1 node pass (H=4, C=64) ----------------
// one warp per dst node; online softmax; epilogue bias+relu -> g_hh (fp16)
__global__ void fused_gat1(const float* __restrict__ att,
                           const float* __restrict__ bias, int N) {
    int warp = (blockIdx.x * blockDim.x + threadIdx.x) >> 5;
    if (warp >= N) return;
    int lane = threadIdx.x & 31;
    int n = warp;
    int c0 = lane * 8;

    const float4* xdp = reinterpret_cast<const float4*>(g_xd1 + (size_t)n * 256 + c0);
    float4 d0 = xdp[0], d1 = xdp[1];
    float4 w0 = *reinterpret_cast<const float4*>(att + c0);
    float4 w1 = *reinterpret_cast<const float4*>(att + c0 + 4);

    float m = -CUDART_INF_F, s = 0.0f;
    float acc[8] = {0, 0, 0, 0, 0, 0, 0, 0};

    int beg = g_rowptr[n], end = g_rowptr[n + 1];
    for (int e = beg; e < end; e++) {
        int src = g_csr_src[e];
        uint4 raw = *reinterpret_cast<const uint4*>(g_xs1h + (size_t)src * 256 + c0);
        float2 f0 = __half22float2(*reinterpret_cast<__half2*>(&raw.x));
        float2 f1 = __half22float2(*reinterpret_cast<__half2*>(&raw.y));
        float2 f2 = __half22float2(*reinterpret_cast<__half2*>(&raw.z));
        float2 f3 = __half22float2(*reinterpret_cast<__half2*>(&raw.w));

        float p = lrelu(f0.x + d0.x) * w0.x + lrelu(f0.y + d0.y) * w0.y
                + lrelu(f1.x + d0.z) * w0.z + lrelu(f1.y + d0.w) * w0.w
                + lrelu(f2.x + d1.x) * w1.x + lrelu(f2.y + d1.y) * w1.y
                + lrelu(f3.x + d1.z) * w1.z + lrelu(f3.y + d1.w) * w1.w;
        p += __shfl_xor_sync(0xffffffffu, p, 4);
        p += __shfl_xor_sync(0xffffffffu, p, 2);
        p += __shfl_xor_sync(0xffffffffu, p, 1);

        float m_new = fmaxf(m, p);
        float scale = __expf(m - m_new);
        float ex    = __expf(p - m_new);
        s = s * scale + ex;
        acc[0] = acc[0] * scale + ex * f0.x;
        acc[1] = acc[1] * scale + ex * f0.y;
        acc[2] = acc[2] * scale + ex * f1.x;
        acc[3] = acc[3] * scale + ex * f1.y;
        acc[4] = acc[4] * scale + ex * f2.x;
        acc[5] = acc[5] * scale + ex * f2.y;
        acc[6] = acc[6] * scale + ex * f3.x;
        acc[7] = acc[7] * scale + ex * f3.y;
        m = m_new;
    }

    float inv = 1.0f / s;
    float4 b0 = *reinterpret_cast<const float4*>(bias + c0);
    float4 b1 = *reinterpret_cast<const float4*>(bias + c0 + 4);
    __half2 h0 = __floats2half2_rn(fmaxf(acc[0] * inv + b0.x, 0.0f),
                                   fmaxf(acc[1] * inv + b0.y, 0.0f));
    __half2 h1 = __floats2half2_rn(fmaxf(acc[2] * inv + b0.z, 0.0f),
                                   fmaxf(acc[3] * inv + b0.w, 0.0f));
    __half2 h2 = __floats2half2_rn(fmaxf(acc[4] * inv + b1.x, 0.0f),
                                   fmaxf(acc[5] * inv + b1.y, 0.0f));
    __half2 h3 = __floats2half2_rn(fmaxf(acc[6] * inv + b1.z, 0.0f),
                                   fmaxf(acc[7] * inv + b1.w, 0.0f));
    uint4 packed = make_uint4(*reinterpret_cast<unsigned*>(&h0),
                              *reinterpret_cast<unsigned*>(&h1),
                              *reinterpret_cast<unsigned*>(&h2),
                              *reinterpret_cast<unsigned*>(&h3));
    *reinterpret_cast<uint4*>(g_hh + (size_t)n * 256 + c0) = packed;
}

// ---------------- fused layer-2 node pass (H=1, C=64) + pool ----------------
__global__ void fused_gat2(const float* __restrict__ att,
                           const float* __restrict__ bias,
                           const int* __restrict__ batch, int N) {
    int warp = (blockIdx.x * blockDim.x + threadIdx.x) >> 5;
    if (warp >= N) return;
    int lane = threadIdx.x & 31;
    int n = warp;
    int c0 = lane * 2;

    float2 d = *reinterpret_cast<const float2*>(g_xd2 + (size_t)n * 64 + c0);
    float2 w = *reinterpret_cast<const float2*>(att + c0);

    float m = -CUDART_INF_F, s = 0.0f;
    float acc0 = 0.0f, acc1 = 0.0f;

    int beg = g_rowptr[n], end = g_rowptr[n + 1];
    for (int e = beg; e < end; e++) {
        int src = g_csr_src[e];
        float2 a = __half22float2(
            *reinterpret_cast<const __half2*>(g_xs2h + (size_t)src * 64 + c0));
        float p = lrelu(a.x + d.x) * w.x + lrelu(a.y + d.y) * w.y;
        p += __shfl_xor_sync(0xffffffffu, p, 16);
        p += __shfl_xor_sync(0xffffffffu, p, 8);
        p += __shfl_xor_sync(0xffffffffu, p, 4);
        p += __shfl_xor_sync(0xffffffffu, p, 2);
        p += __shfl_xor_sync(0xffffffffu, p, 1);

        float m_new = fmaxf(m, p);
        float scale = __expf(m - m_new);
        float ex    = __expf(p - m_new);
        s = s * scale + ex;
        acc0 = acc0 * scale + ex * a.x;
        acc1 = acc1 * scale + ex * a.y;
        m = m_new;
    }

    float inv = 1.0f / s;
    float v0 = acc0 * inv + bias[c0];
    float v1 = acc1 * inv + bias[c0 + 1];

    int g = batch[n];
    atomicAdd(&g_pool[g * 64 + c0], v0);
    atomicAdd(&g_pool[g * 64 + c0 + 1], v1);
    if (lane == 0) atomicAdd(&g_cnt[g], 1.0f);
}

__global__ void final_kernel(const float* __restrict__ Wlin,
                             const float* __restrict__ blin,
                             float* __restrict__ out) {
    int g = threadIdx.x;
    if (g >= NG) return;
    float cnt = g_cnt[g];
    if (cnt < 1.0f) cnt = 1.0f;
    float sum = 0.0f;
#pragma unroll
    for (int c = 0; c < 64; c++)
        sum += (g_pool[g * 64 + c] / cnt) * Wlin[c];
    out[g] = sum + blin[0];
}

// ---------------- launcher ----------------
extern "C" void kernel_launch(void* const* d_in, const int* in_sizes, int n_in,
                              void* d_out, int out_size) {
    const float* x      = (const float*)d_in[0];
    const int*   ei     = (const int*)d_in[1];
    const int*   batch  = (const int*)d_in[2];
    const float* W_l1   = (const float*)d_in[3];
    const float* b_l1   = (const float*)d_in[4];
    const float* W_r1   = (const float*)d_in[5];
    const float* b_r1   = (const float*)d_in[6];
    const float* att1   = (const float*)d_in[7];
    const float* bias1  = (const float*)d_in[8];
    const float* W_l2   = (const float*)d_in[9];
    const float* b_l2   = (const float*)d_in[10];
    const float* W_r2   = (const float*)d_in[11];
    const float* b_r2   = (const float*)d_in[12];
    const float* att2   = (const float*)d_in[13];
    const float* bias2  = (const float*)d_in[14];
    const float* W_lin  = (const float*)d_in[15];
    const float* b_lin  = (const float*)d_in[16];
    float* out = (float*)d_out;

    const int N = in_sizes[0] / 128;   // 50000
    const int E = in_sizes[1] / 2;     // 800000
    const int ET = E + N;

    // __device__ symbols -> real device pointers (host-side query; capture-safe)
    __half *p_xh, *p_xs1h, *p_hh, *p_xs2h;
    float *p_xd1, *p_xd2;
    cudaGetSymbolAddress((void**)&p_xh,    g_xh);
    cudaGetSymbolAddress((void**)&p_xs1h,  g_xs1h);
    cudaGetSymbolAddress((void**)&p_xd1,   g_xd1);
    cudaGetSymbolAddress((void**)&p_hh,    g_hh);
    cudaGetSymbolAddress((void**)&p_xs2h,  g_xs2h);
    cudaGetSymbolAddress((void**)&p_xd2,   g_xd2);

    // init + convert x to fp16 + CSR build
    zero_kernel<<<256, 256>>>(N);
    f2h_kernel<<<1024, 256>>>(x, (size_t)N * 128 / 4);
    hist_kernel<<<(ET + 255) / 256, 256>>>(ei, E, N);
    scan_kernel<<<1, 1024>>>(N);
    scatter_kernel<<<(ET + 255) / 256, 256>>>(ei, E, N);

    const int mblocks = (N + 127) / 128;

    // layer 1 transforms (z=0 -> half xs1, z=1 -> float xd1)
    {
        dim3 grid(256 / 64, mblocks, 2);
        gemm_f16_dual<<<grid, 256>>>(p_xh, W_l1, b_l1, p_xs1h, W_r1, b_r1, p_xd1,
                                     N, 128, 256);
    }

    // fused layer-1 attention + aggregation (+ bias + relu) -> fp16 h
    fused_gat1<<<(N * 32 + 255) / 256, 256>>>(att1, bias1, N);

    // layer 2 transforms (A = fp16 h)
    {
        dim3 grid(1, mblocks, 2);
        gemm_f16_dual<<<grid, 256>>>(p_hh, W_l2, b_l2, p_xs2h, W_r2, b_r2, p_xd2,
                                     N, 256, 64);
    }

    // fused layer-2 attention + aggregation + pooling
    fused_gat2<<<(N * 32 + 255) / 256, 256>>>(att2, bias2, batch, N);

    final_kernel<<<1, 64>>>(W_lin, b_lin, out);
}

// round 9
// speedup vs baseline: 1.3251x; 1.2092x over previous
#include <cuda_runtime.h>
#include <cuda_fp16.h>
#include <cstdint>
#include <math_constants.h>

// ---------------- problem-size constants ----------------
#define MAXN 50000
#define MAXE 800000
#define MAXET (MAXE + MAXN)   // edges + self loops
#define NG 64                 // graphs
#define SCAN_CHUNK 512
#define MAX_SCAN_BLOCKS 128   // ceil(50000/512)=98 <= 128

// ---------------- scratch (device globals; allocation-free) ----------------
__device__ __align__(16) __half g_xh  [(size_t)MAXN * 128];  // fp16 copy of x
__device__ __align__(16) __half g_xs1h[(size_t)MAXN * 256];  // fp16 xs, layer 1
__device__ __align__(16) float  g_xd1 [(size_t)MAXN * 256];
__device__ __align__(16) __half g_hh  [(size_t)MAXN * 256];  // fp16 h (layer-1 out)
__device__ __align__(16) __half g_xs2h[(size_t)MAXN * 64];   // fp16 xs, layer 2
__device__ __align__(16) float  g_xd2 [(size_t)MAXN * 64];

__device__ int   g_deg[MAXN];
__device__ int   g_rowptr[MAXN + 1];
__device__ int   g_cursor[MAXN];
__device__ int   g_csr_src[MAXET];
__device__ int   g_bsum[MAX_SCAN_BLOCKS];
__device__ int   g_boff[MAX_SCAN_BLOCKS];

__device__ float g_pool[NG * 64];
__device__ float g_cnt[NG];

__device__ __forceinline__ float lrelu(float v) {
    return v > 0.0f ? v : 0.2f * v;
}

// fp16 mma: D(f32) += A(f16) * B(f16), 16x8x16
__device__ __forceinline__ void mma_f16(float* c, const unsigned* a, const unsigned* b) {
    asm volatile(
        "mma.sync.aligned.m16n8k16.row.col.f32.f16.f16.f32 "
        "{%0,%1,%2,%3}, {%4,%5,%6,%7}, {%8,%9}, {%0,%1,%2,%3};"
        : "+f"(c[0]), "+f"(c[1]), "+f"(c[2]), "+f"(c[3])
        : "r"(a[0]), "r"(a[1]), "r"(a[2]), "r"(a[3]), "r"(b[0]), "r"(b[1]));
}

// ---------------- zero / init ----------------
__global__ void zero_kernel(int N) {
    int i = blockIdx.x * blockDim.x + threadIdx.x;
    int stride = gridDim.x * blockDim.x;
    for (int k = i; k < N; k += stride) g_deg[k] = 0;
    if (i < NG * 64) g_pool[i] = 0.0f;
    if (i < NG)      g_cnt[i] = 0.0f;
}

// fp32 -> fp16 convert (x), 4 elems/thread
__global__ void f2h_kernel(const float* __restrict__ in, size_t total4) {
    size_t i = (size_t)blockIdx.x * blockDim.x + threadIdx.x;
    size_t stride = (size_t)gridDim.x * blockDim.x;
    for (; i < total4; i += stride) {
        float4 v = reinterpret_cast<const float4*>(in)[i];
        __half2 h0 = __floats2half2_rn(v.x, v.y);
        __half2 h1 = __floats2half2_rn(v.z, v.w);
        reinterpret_cast<uint2*>(g_xh)[i] =
            make_uint2(*reinterpret_cast<unsigned*>(&h0), *reinterpret_cast<unsigned*>(&h1));
    }
}

// ---------------- CSR build ----------------
__global__ void hist_kernel(const int* __restrict__ ei, int E, int N) {
    int i = blockIdx.x * blockDim.x + threadIdx.x;
    int ET = E + N;
    if (i >= ET) return;
    int d = (i < E) ? ei[E + i] : (i - E);
    atomicAdd(&g_deg[d], 1);
}

// phase A: per-block sum of 512 degrees
__global__ void scan_a(int N) {
    __shared__ int red[256];
    int b = blockIdx.x, t = threadIdx.x;
    int i0 = b * SCAN_CHUNK + 2 * t;
    int s = 0;
    if (i0 < N)     s += g_deg[i0];
    if (i0 + 1 < N) s += g_deg[i0 + 1];
    red[t] = s;
    __syncthreads();
#pragma unroll
    for (int off = 128; off > 0; off >>= 1) {
        if (t < off) red[t] += red[t + off];
        __syncthreads();
    }
    if (t == 0) g_bsum[b] = red[0];
}

// phase B: single-block exclusive scan of block sums (+ rowptr[N])
__global__ void scan_b(int NB, int N) {
    __shared__ int ss[MAX_SCAN_BLOCKS];
    int t = threadIdx.x;
    int v = (t < NB) ? g_bsum[t] : 0;
    ss[t] = v;
    __syncthreads();
#pragma unroll
    for (int off = 1; off < MAX_SCAN_BLOCKS; off <<= 1) {
        int u = (t >= off) ? ss[t - off] : 0;
        __syncthreads();
        ss[t] += u;
        __syncthreads();
    }
    if (t < NB) g_boff[t] = ss[t] - v;
    if (t == MAX_SCAN_BLOCKS - 1) g_rowptr[N] = ss[MAX_SCAN_BLOCKS - 1];
}

// phase C: per-block local scan + global offset -> rowptr/cursor
__global__ void scan_c(int N) {
    __shared__ int ss[256];
    int b = blockIdx.x, t = threadIdx.x;
    int i0 = b * SCAN_CHUNK + 2 * t;
    int d0 = (i0 < N)     ? g_deg[i0]     : 0;
    int d1 = (i0 + 1 < N) ? g_deg[i0 + 1] : 0;
    int tsum = d0 + d1;
    ss[t] = tsum;
    __syncthreads();
#pragma unroll
    for (int off = 1; off < 256; off <<= 1) {
        int u = (t >= off) ? ss[t - off] : 0;
        __syncthreads();
        ss[t] += u;
        __syncthreads();
    }
    int off0 = g_boff[b] + ss[t] - tsum;
    if (i0 < N)     { g_rowptr[i0]     = off0;      g_cursor[i0]     = off0; }
    if (i0 + 1 < N) { g_rowptr[i0 + 1] = off0 + d0; g_cursor[i0 + 1] = off0 + d0; }
}

__global__ void scatter_kernel(const int* __restrict__ ei, int E, int N) {
    int i = blockIdx.x * blockDim.x + threadIdx.x;
    int ET = E + N;
    if (i >= ET) return;
    int s, d;
    if (i < E) { s = ei[i]; d = ei[E + i]; }
    else       { s = i - E; d = s; }
    int pos = atomicAdd(&g_cursor[d], 1);
    g_csr_src[pos] = s;
}

// ---------------- fp16 tensor-core GEMM ----------------
// C[M,Ncol] = A[M,K](f16) @ W[K,Ncol](f32->f16) + bias
// Tile: BM=128, BN=64, BK=32; 256 threads = 8 warps (4m x 2n), m16n8k16.
// blockIdx.z==0 -> HALF output (xs), z==1 -> FLOAT output (xd).
__global__ void gemm_f16_dual(const __half* __restrict__ A,
                              const float* __restrict__ W0, const float* __restrict__ b0,
                              __half* __restrict__ C0h,
                              const float* __restrict__ W1, const float* __restrict__ b1,
                              float* __restrict__ C1,
                              int M, int K, int Ncol) {
    const float* W    = blockIdx.z ? W1 : W0;
    const float* bias = blockIdx.z ? b1 : b0;

    __shared__ __half As[128][40];
    __shared__ __half Bs[64][40];

    const int t    = threadIdx.x;
    const int lane = t & 31;
    const int warp = t >> 5;
    const int grp  = lane >> 2;
    const int tg   = lane & 3;
    const int warp_m = warp & 3;
    const int warp_n = warp >> 2;

    const int row0 = blockIdx.y * 128;
    const int col0 = blockIdx.x * 64;

    float acc[2][4][4];
#pragma unroll
    for (int mi = 0; mi < 2; mi++)
#pragma unroll
        for (int ni = 0; ni < 4; ni++)
#pragma unroll
            for (int j = 0; j < 4; j++) acc[mi][ni][j] = 0.0f;

    for (int k0 = 0; k0 < K; k0 += 32) {
#pragma unroll
        for (int i = 0; i < 2; i++) {
            int idx = t + i * 256;
            int r  = idx >> 2;
            int c8 = idx & 3;
            int gr = row0 + r;
            uint4 v = make_uint4(0u, 0u, 0u, 0u);
            if (gr < M)
                v = *reinterpret_cast<const uint4*>(&A[(size_t)gr * K + k0 + c8 * 8]);
            *reinterpret_cast<uint4*>(&As[r][c8 * 8]) = v;
        }
#pragma unroll
        for (int i = 0; i < 2; i++) {
            int idx = t + i * 256;
            int kk = idx >> 4;
            int c4 = idx & 15;
            float4 v = *reinterpret_cast<const float4*>(&W[(size_t)(k0 + kk) * Ncol + col0 + c4 * 4]);
            int c = c4 * 4;
            Bs[c + 0][kk] = __float2half_rn(v.x);
            Bs[c + 1][kk] = __float2half_rn(v.y);
            Bs[c + 2][kk] = __float2half_rn(v.z);
            Bs[c + 3][kk] = __float2half_rn(v.w);
        }
        __syncthreads();

#pragma unroll
        for (int ks = 0; ks < 32; ks += 16) {
            unsigned af[2][4];
#pragma unroll
            for (int mi = 0; mi < 2; mi++) {
                int r = warp_m * 32 + mi * 16 + grp;
                af[mi][0] = *reinterpret_cast<const unsigned*>(&As[r][ks + 2 * tg]);
                af[mi][1] = *reinterpret_cast<const unsigned*>(&As[r + 8][ks + 2 * tg]);
                af[mi][2] = *reinterpret_cast<const unsigned*>(&As[r][ks + 2 * tg + 8]);
                af[mi][3] = *reinterpret_cast<const unsigned*>(&As[r + 8][ks + 2 * tg + 8]);
            }
            unsigned bf[4][2];
#pragma unroll
            for (int ni = 0; ni < 4; ni++) {
                int c = warp_n * 32 + ni * 8 + grp;
                bf[ni][0] = *reinterpret_cast<const unsigned*>(&Bs[c][ks + 2 * tg]);
                bf[ni][1] = *reinterpret_cast<const unsigned*>(&Bs[c][ks + 2 * tg + 8]);
            }
#pragma unroll
            for (int mi = 0; mi < 2; mi++)
#pragma unroll
                for (int ni = 0; ni < 4; ni++)
                    mma_f16(acc[mi][ni], af[mi], bf[ni]);
        }
        __syncthreads();
    }

    const bool half_out = (blockIdx.z == 0);
#pragma unroll
    for (int ni = 0; ni < 4; ni++) {
        int gc = col0 + warp_n * 32 + ni * 8 + tg * 2;
        float2 bv = *reinterpret_cast<const float2*>(&bias[gc]);
#pragma unroll
        for (int mi = 0; mi < 2; mi++) {
            int gr = row0 + warp_m * 32 + mi * 16 + grp;
            if (gr < M) {
                float ox = acc[mi][ni][0] + bv.x;
                float oy = acc[mi][ni][1] + bv.y;
                if (half_out)
                    *reinterpret_cast<__half2*>(&C0h[(size_t)gr * Ncol + gc]) =
                        __floats2half2_rn(ox, oy);
                else
                    *reinterpret_cast<float2*>(&C1[(size_t)gr * Ncol + gc]) =
                        make_float2(ox, oy);
            }
            if (gr + 8 < M) {
                float ox = acc[mi][ni][2] + bv.x;
                float oy = acc[mi][ni][3] + bv.y;
                if (half_out)
                    *reinterpret_cast<__half2*>(&C0h[(size_t)(gr + 8) * Ncol + gc]) =
                        __floats2half2_rn(ox, oy);
                else
                    *reinterpret_cast<float2*>(&C1[(size_t)(gr + 8) * Ncol + gc]) =
                        make_float2(ox, oy);
            }
        }
    }
}

// ---------------- fused layer-1 node pass (H=4, C=64) ----------------
__global__ void fused_gat1(const float* __restrict__ att,
                           const float* __restrict__ bias, int N) {
    int warp = (blockIdx.x * blockDim.x + threadIdx.x) >> 5;
    if (warp >= N) return;
    int lane = threadIdx.x & 31;
    int n = warp;
    int c0 = lane * 8;

    const float4* xdp = reinterpret_cast<const float4*>(g_xd1 + (size_t)n * 256 + c0);
    float4 d0 = xdp[0], d1 = xdp[1];
    float4 w0 = *reinterpret_cast<const float4*>(att + c0);
    float4 w1 = *reinterpret_cast<const float4*>(att + c0 + 4);

    float m = -CUDART_INF_F, s = 0.0f;
    float acc[8] = {0, 0, 0, 0, 0, 0, 0, 0};

    int beg = g_rowptr[n], end = g_rowptr[n + 1];
    for (int e = beg; e < end; e++) {
        int src = g_csr_src[e];
        uint4 raw = *reinterpret_cast<const uint4*>(g_xs1h + (size_t)src * 256 + c0);
        float2 f0 = __half22float2(*reinterpret_cast<__half2*>(&raw.x));
        float2 f1 = __half22float2(*reinterpret_cast<__half2*>(&raw.y));
        float2 f2 = __half22float2(*reinterpret_cast<__half2*>(&raw.z));
        float2 f3 = __half22float2(*reinterpret_cast<__half2*>(&raw.w));

        float p = lrelu(f0.x + d0.x) * w0.x + lrelu(f0.y + d0.y) * w0.y
                + lrelu(f1.x + d0.z) * w0.z + lrelu(f1.y + d0.w) * w0.w
                + lrelu(f2.x + d1.x) * w1.x + lrelu(f2.y + d1.y) * w1.y
                + lrelu(f3.x + d1.z) * w1.z + lrelu(f3.y + d1.w) * w1.w;
        p += __shfl_xor_sync(0xffffffffu, p, 4);
        p += __shfl_xor_sync(0xffffffffu, p, 2);
        p += __shfl_xor_sync(0xffffffffu, p, 1);

        float m_new = fmaxf(m, p);
        float scale = __expf(m - m_new);
        float ex    = __expf(p - m_new);
        s = s * scale + ex;
        acc[0] = acc[0] * scale + ex * f0.x;
        acc[1] = acc[1] * scale + ex * f0.y;
        acc[2] = acc[2] * scale + ex * f1.x;
        acc[3] = acc[3] * scale + ex * f1.y;
        acc[4] = acc[4] * scale + ex * f2.x;
        acc[5] = acc[5] * scale + ex * f2.y;
        acc[6] = acc[6] * scale + ex * f3.x;
        acc[7] = acc[7] * scale + ex * f3.y;
        m = m_new;
    }

    float inv = 1.0f / s;
    float4 b0 = *reinterpret_cast<const float4*>(bias + c0);
    float4 b1 = *reinterpret_cast<const float4*>(bias + c0 + 4);
    __half2 h0 = __floats2half2_rn(fmaxf(acc[0] * inv + b0.x, 0.0f),
                                   fmaxf(acc[1] * inv + b0.y, 0.0f));
    __half2 h1 = __floats2half2_rn(fmaxf(acc[2] * inv + b0.z, 0.0f),
                                   fmaxf(acc[3] * inv + b0.w, 0.0f));
    __half2 h2 = __floats2half2_rn(fmaxf(acc[4] * inv + b1.x, 0.0f),
                                   fmaxf(acc[5] * inv + b1.y, 0.0f));
    __half2 h3 = __floats2half2_rn(fmaxf(acc[6] * inv + b1.z, 0.0f),
                                   fmaxf(acc[7] * inv + b1.w, 0.0f));
    uint4 packed = make_uint4(*reinterpret_cast<unsigned*>(&h0),
                              *reinterpret_cast<unsigned*>(&h1),
                              *reinterpret_cast<unsigned*>(&h2),
                              *reinterpret_cast<unsigned*>(&h3));
    *reinterpret_cast<uint4*>(g_hh + (size_t)n * 256 + c0) = packed;
}

// ---------------- fused layer-2 node pass (H=1, C=64) + pool ----------------
__global__ void fused_gat2(const float* __restrict__ att,
                           const float* __restrict__ bias,
                           const int* __restrict__ batch, int N) {
    int warp = (blockIdx.x * blockDim.x + threadIdx.x) >> 5;
    if (warp >= N) return;
    int lane = threadIdx.x & 31;
    int n = warp;
    int c0 = lane * 2;

    float2 d = *reinterpret_cast<const float2*>(g_xd2 + (size_t)n * 64 + c0);
    float2 w = *reinterpret_cast<const float2*>(att + c0);

    float m = -CUDART_INF_F, s = 0.0f;
    float acc0 = 0.0f, acc1 = 0.0f;

    int beg = g_rowptr[n], end = g_rowptr[n + 1];
    for (int e = beg; e < end; e++) {
        int src = g_csr_src[e];
        float2 a = __half22float2(
            *reinterpret_cast<const __half2*>(g_xs2h + (size_t)src * 64 + c0));
        float p = lrelu(a.x + d.x) * w.x + lrelu(a.y + d.y) * w.y;
        p += __shfl_xor_sync(0xffffffffu, p, 16);
        p += __shfl_xor_sync(0xffffffffu, p, 8);
        p += __shfl_xor_sync(0xffffffffu, p, 4);
        p += __shfl_xor_sync(0xffffffffu, p, 2);
        p += __shfl_xor_sync(0xffffffffu, p, 1);

        float m_new = fmaxf(m, p);
        float scale = __expf(m - m_new);
        float ex    = __expf(p - m_new);
        s = s * scale + ex;
        acc0 = acc0 * scale + ex * a.x;
        acc1 = acc1 * scale + ex * a.y;
        m = m_new;
    }

    float inv = 1.0f / s;
    float v0 = acc0 * inv + bias[c0];
    float v1 = acc1 * inv + bias[c0 + 1];

    int g = batch[n];
    atomicAdd(&g_pool[g * 64 + c0], v0);
    atomicAdd(&g_pool[g * 64 + c0 + 1], v1);
    if (lane == 0) atomicAdd(&g_cnt[g], 1.0f);
}

__global__ void final_kernel(const float* __restrict__ Wlin,
                             const float* __restrict__ blin,
                             float* __restrict__ out) {
    int g = threadIdx.x;
    if (g >= NG) return;
    float cnt = g_cnt[g];
    if (cnt < 1.0f) cnt = 1.0f;
    float sum = 0.0f;
#pragma unroll
    for (int c = 0; c < 64; c++)
        sum += (g_pool[g * 64 + c] / cnt) * Wlin[c];
    out[g] = sum + blin[0];
}

// ---------------- launcher ----------------
extern "C" void kernel_launch(void* const* d_in, const int* in_sizes, int n_in,
                              void* d_out, int out_size) {
    const float* x      = (const float*)d_in[0];
    const int*   ei     = (const int*)d_in[1];
    const int*   batch  = (const int*)d_in[2];
    const float* W_l1   = (const float*)d_in[3];
    const float* b_l1   = (const float*)d_in[4];
    const float* W_r1   = (const float*)d_in[5];
    const float* b_r1   = (const float*)d_in[6];
    const float* att1   = (const float*)d_in[7];
    const float* bias1  = (const float*)d_in[8];
    const float* W_l2   = (const float*)d_in[9];
    const float* b_l2   = (const float*)d_in[10];
    const float* W_r2   = (const float*)d_in[11];
    const float* b_r2   = (const float*)d_in[12];
    const float* att2   = (const float*)d_in[13];
    const float* bias2  = (const float*)d_in[14];
    const float* W_lin  = (const float*)d_in[15];
    const float* b_lin  = (const float*)d_in[16];
    float* out = (float*)d_out;

    const int N = in_sizes[0] / 128;   // 50000
    const int E = in_sizes[1] / 2;     // 800000
    const int ET = E + N;
    const int NB = (N + SCAN_CHUNK - 1) / SCAN_CHUNK;   // 98

    // __device__ symbols -> real device pointers (host-side query; capture-safe)
    __half *p_xh, *p_xs1h, *p_hh, *p_xs2h;
    float *p_xd1, *p_xd2;
    cudaGetSymbolAddress((void**)&p_xh,    g_xh);
    cudaGetSymbolAddress((void**)&p_xs1h,  g_xs1h);
    cudaGetSymbolAddress((void**)&p_xd1,   g_xd1);
    cudaGetSymbolAddress((void**)&p_hh,    g_hh);
    cudaGetSymbolAddress((void**)&p_xs2h,  g_xs2h);
    cudaGetSymbolAddress((void**)&p_xd2,   g_xd2);

    // init + convert x to fp16 + CSR build (parallel 3-phase scan)
    zero_kernel<<<256, 256>>>(N);
    f2h_kernel<<<1024, 256>>>(x, (size_t)N * 128 / 4);
    hist_kernel<<<(ET + 255) / 256, 256>>>(ei, E, N);
    scan_a<<<NB, 256>>>(N);
    scan_b<<<1, MAX_SCAN_BLOCKS>>>(NB, N);
    scan_c<<<NB, 256>>>(N);
    scatter_kernel<<<(ET + 255) / 256, 256>>>(ei, E, N);

    const int mblocks = (N + 127) / 128;

    // layer 1 transforms (z=0 -> half xs1, z=1 -> float xd1)
    {
        dim3 grid(256 / 64, mblocks, 2);
        gemm_f16_dual<<<grid, 256>>>(p_xh, W_l1, b_l1, p_xs1h, W_r1, b_r1, p_xd1,
                                     N, 128, 256);
    }

    // fused layer-1 attention + aggregation (+ bias + relu) -> fp16 h
    fused_gat1<<<(N * 32 + 255) / 256, 256>>>(att1, bias1, N);

    // layer 2 transforms (A = fp16 h)
    {
        dim3 grid(1, mblocks, 2);
        gemm_f16_dual<<<grid, 256>>>(p_hh, W_l2, b_l2, p_xs2h, W_r2, b_r2, p_xd2,
                                     N, 256, 64);
    }

    // fused layer-2 attention + aggregation + pooling
    fused_gat2<<<(N * 32 + 255) / 256, 256>>>(att2, bias2, batch, N);

    final_kernel<<<1, 64>>>(W_lin, b_lin, out);
}